// round 15
// baseline (speedup 1.0000x reference)
#include <cuda_runtime.h>
#include <cuda_fp16.h>
#include <cuda_bf16.h>
#include <cstdint>

#define NN 50000
#define NE 800000
#define C 128
#define M_PAD 50048   /* 391 * 128 */
#define SETUP_B 196   /* ceil(NN/256) */
#define NTILE (M_PAD / 128)   /* 391 */
#define BCAP 64       /* bucket capacity; max in-degree (Poisson mean 16) << 64 */
#define FILL_T (NE / 4)       /* 200000 threads, 4 edges each */

#define PKW 68        /* u32 pitch of one bf16 tile row (136 bf16 = 272 B) */
#define IMG_U32 (128 * PKW)          /* 8704 u32 per 128x128 bf16 image */
#define IMG_BYTES (IMG_U32 * 4)      /* 34816 B */
#define SM_TOTAL (4 * IMG_BYTES)     /* Ahi, Alo, Whi, Wlo = 139264 B */

// ---------------- device scratch (static, no allocation) ----------------
__device__ int      g_is64;
__device__ int      g_cursor[NN];               // 0-init; post-fill = in-degree
__device__ int      g_bucket[(size_t)NN * BCAP];// per-node src lists (256B/node)
__device__ __half   g_h[(size_t)M_PAD * C];     // dinv-scaled gather table t
__device__ float    g_buf1[(size_t)M_PAD * C];  // aggregated activations (fp32)
// W images: [W1hi, W1lo, W2hi, W2lo]; row-major n x k bf16, pitch PKW u32.
__device__ uint32_t g_Wimg[4][IMG_U32];

// ---------------- small helpers ----------------
__device__ __forceinline__ uint32_t smem_u32(const void* p) {
    uint32_t a;
    asm("{ .reg .u64 t; cvta.to.shared.u64 t, %1; cvt.u32.u64 %0, t; }" : "=r"(a) : "l"(p));
    return a;
}
__device__ __forceinline__ uint32_t pack_bf16(float lo_elem, float hi_elem) {
    __nv_bfloat162 t = __floats2bfloat162_rn(lo_elem, hi_elem);  // .x = first arg
    return *reinterpret_cast<uint32_t*>(&t);
}
__device__ __forceinline__ void ldsm_x4(uint32_t* r, uint32_t addr) {
    asm volatile("ldmatrix.sync.aligned.m8n8.x4.shared.b16 {%0,%1,%2,%3}, [%4];"
                 : "=r"(r[0]), "=r"(r[1]), "=r"(r[2]), "=r"(r[3]) : "r"(addr));
}
__device__ __forceinline__ void mma_bf16(float* c, const uint32_t* a, uint32_t b0, uint32_t b1) {
    asm volatile(
        "mma.sync.aligned.m16n8k16.row.col.f32.bf16.bf16.f32 "
        "{%0,%1,%2,%3}, {%4,%5,%6,%7}, {%8,%9}, {%0,%1,%2,%3};"
        : "+f"(c[0]), "+f"(c[1]), "+f"(c[2]), "+f"(c[3])
        : "r"(a[0]), "r"(a[1]), "r"(a[2]), "r"(a[3]), "r"(b0), "r"(b1));
}
__device__ __forceinline__ int edge_at(const void* ei, int is64, long long idx) {
    return is64 ? (int)((const long long*)ei)[idx] : ((const int*)ei)[idx];
}

// ---------------- setup: probe + cursor clear + W prep (one launch) ---------
__global__ void k_setup(const unsigned int* __restrict__ ei_w,
                        const float* __restrict__ W1, const float* __restrict__ W2) {
    int t = threadIdx.x;
    int gid = blockIdx.x * 256 + t;

    if (blockIdx.x == 0 && t < 32) {
        unsigned int acc = 0;
        #pragma unroll
        for (int i = 0; i < 32; ++i) acc |= ei_w[2 * (t + 32 * i) + 1];
        int any = __any_sync(0xFFFFFFFFu, acc != 0);
        if (t == 0) g_is64 = !any;
    }
    if (gid < NN) g_cursor[gid] = 0;
    if (gid < 16384) {
        int m  = gid >> 13;
        int p  = gid & 8191;
        int n  = p >> 6;
        int kp = p & 63;
        const float* W = m ? W2 : W1;
        float v0 = W[(2 * kp) * C + n];
        float v1 = W[(2 * kp + 1) * C + n];
        float h0 = __bfloat162float(__float2bfloat16_rn(v0));
        float h1 = __bfloat162float(__float2bfloat16_rn(v1));
        g_Wimg[m * 2 + 0][n * PKW + kp] = pack_bf16(h0, h1);
        g_Wimg[m * 2 + 1][n * PKW + kp] = pack_bf16(v0 - h0, v1 - h1);
    }
}

// ---------------- bucket fill: 4 edges/thread for atomic-latency MLP --------
__global__ void k_fill(const void* __restrict__ ei) {
    int t = blockIdx.x * blockDim.x + threadIdx.x;
    if (t >= FILL_T) return;
    int is64 = g_is64;
    int s[4], d[4], pos[4];
    #pragma unroll
    for (int k = 0; k < 4; ++k) {
        int e = t + FILL_T * k;                      // coalesced within phase
        s[k] = edge_at(ei, is64, e);
        d[k] = edge_at(ei, is64, (long long)NE + e);
    }
    #pragma unroll
    for (int k = 0; k < 4; ++k)
        pos[k] = atomicAdd(&g_cursor[d[k]], 1);      // 4 independent atomics
    #pragma unroll
    for (int k = 0; k < 4; ++k)
        g_bucket[(size_t)d[k] * BCAP + pos[k]] = s[k];
}

// ---------------- HMMA GEMM: g_h[tile] = dinv .* (A @ W) --------------------
// 512 threads / 16 warps; warp tile 64x16 (4x8 layout) for latency hiding.
__global__ void __launch_bounds__(512, 1) k_gemm(const float* __restrict__ Aext, int wsel) {
    extern __shared__ char smem[];
    uint32_t* Ahi = (uint32_t*)smem;
    uint32_t* Alo = Ahi + IMG_U32;
    const uint32_t sb = smem_u32(smem);
    const int tid = threadIdx.x;
    const int row0 = blockIdx.x * 128;
    const float* __restrict__ A = Aext ? Aext : g_buf1;

    #pragma unroll
    for (int i = 0; i < 16; ++i) {
        int p  = tid + 512 * i;        // 0..8191
        int r  = p >> 6;
        int kp = p & 63;
        int grow = row0 + r;
        float2 v = make_float2(0.f, 0.f);
        if (grow < NN) v = ((const float2*)A)[(size_t)grow * 64 + kp];
        float h0 = __bfloat162float(__float2bfloat16_rn(v.x));
        float h1 = __bfloat162float(__float2bfloat16_rn(v.y));
        Ahi[r * PKW + kp] = pack_bf16(h0, h1);
        Alo[r * PKW + kp] = pack_bf16(v.x - h0, v.y - h1);
    }
    {
        const uint4* sh = (const uint4*)g_Wimg[wsel * 2 + 0];
        const uint4* sl = (const uint4*)g_Wimg[wsel * 2 + 1];
        uint4* dh = (uint4*)(smem + 2 * IMG_BYTES);
        uint4* dl = (uint4*)(smem + 3 * IMG_BYTES);
        #pragma unroll
        for (int i = 0; i < 5; ++i) {
            int x = tid + 512 * i;     // 0..2559, bound 2176 uint4
            if (x < IMG_BYTES / 16) { dh[x] = sh[x]; dl[x] = sl[x]; }
        }
    }
    __syncthreads();

    const int wid  = tid >> 5;
    const int lane = tid & 31;
    const int rm = (wid & 1) * 64;     // warp row base  (2 rows of warps)
    const int nb = (wid >> 1) * 16;    // warp col base  (8 cols of warps)

    const int row_off = (lane & 7) + ((lane >> 3) & 1) * 8;
    const int kqA = lane >> 4;
    uint32_t ao[4];
    #pragma unroll
    for (int mi = 0; mi < 4; ++mi)
        ao[mi] = ((rm + mi * 16 + row_off) * PKW + kqA * 4) * 4;
    const int n_off = (lane & 7) + ((lane & 16) ? 8 : 0);
    const int kqB = (lane >> 3) & 1;
    const uint32_t bo = ((nb + n_off) * PKW + kqB * 4) * 4;   // one n16 ldsm

    float acc[4][2][4];
    #pragma unroll
    for (int mi = 0; mi < 4; ++mi)
        #pragma unroll
        for (int ni = 0; ni < 2; ++ni)
            #pragma unroll
            for (int q = 0; q < 4; ++q) acc[mi][ni][q] = 0.0f;

    const uint32_t pa[3] = {0, 0, 1}, pb[3] = {0, 1, 0};
    #pragma unroll
    for (int pr = 0; pr < 3; ++pr) {
        uint32_t abase = sb + pa[pr] * IMG_BYTES;
        uint32_t bbase = sb + 2 * IMG_BYTES + pb[pr] * IMG_BYTES;
        #pragma unroll
        for (int ks = 0; ks < 8; ++ks) {
            uint32_t koff = ks * 32;   // 16 bf16 = 32 B
            uint32_t a[4][4], b[4];
            #pragma unroll
            for (int mi = 0; mi < 4; ++mi) ldsm_x4(a[mi], abase + ao[mi] + koff);
            ldsm_x4(b, bbase + bo + koff);
            #pragma unroll
            for (int mi = 0; mi < 4; ++mi)
                #pragma unroll
                for (int ni = 0; ni < 2; ++ni)
                    mma_bf16(acc[mi][ni], a[mi], b[2 * ni], b[2 * ni + 1]);
        }
    }

    // epilogue: dinv[row] = rsqrt(deg+1) straight from cursor; store fp16 table
    #pragma unroll
    for (int mi = 0; mi < 4; ++mi) {
        int row = row0 + rm + mi * 16 + (lane >> 2);
        float dv0 = (row     < NN) ? rsqrtf((float)(g_cursor[row]     + 1)) : 0.0f;
        float dv1 = (row + 8 < NN) ? rsqrtf((float)(g_cursor[row + 8] + 1)) : 0.0f;
        #pragma unroll
        for (int ni = 0; ni < 2; ++ni) {
            int col = nb + ni * 8 + (lane & 3) * 2;
            __half2 lo = __float22half2_rn(make_float2(acc[mi][ni][0] * dv0,
                                                       acc[mi][ni][1] * dv0));
            __half2 hi = __float22half2_rn(make_float2(acc[mi][ni][2] * dv1,
                                                       acc[mi][ni][3] * dv1));
            *(__half2*)(g_h + (size_t)row * C + col)       = lo;
            *(__half2*)(g_h + (size_t)(row + 8) * C + col) = hi;
        }
    }
}

// ---------------- Aggregation: warp per node, fp16-pair pre-sum -------------
// out[d] = relu( dinv[d] * (Σ_in t[src] + t[d]) + b )
__device__ __forceinline__ float4 gather_row(int row, int lane) {
    uint2 u = *(const uint2*)(g_h + (size_t)row * C + lane * 4);
    __half2 a = *(__half2*)&u.x, b = *(__half2*)&u.y;
    float2 f0 = __half22float2(a), f1 = __half22float2(b);
    return make_float4(f0.x, f0.y, f1.x, f1.y);
}
__device__ __forceinline__ float4 agg_node(int gw, int lane, int deg) {
    float4 acc = gather_row(gw, lane);              // self-loop term t[d]
    const int* __restrict__ bk = g_bucket + (size_t)gw * BCAP;
    const char* tb = (const char*)g_h + lane * 8;
    int j = 0;
    #pragma unroll 2
    for (; j + 2 <= deg; j += 2) {
        uint2 ua = *(const uint2*)(tb + (size_t)bk[j]     * 256);
        uint2 ub = *(const uint2*)(tb + (size_t)bk[j + 1] * 256);
        __half2 p0 = __hadd2(*(__half2*)&ua.x, *(__half2*)&ub.x);
        __half2 p1 = __hadd2(*(__half2*)&ua.y, *(__half2*)&ub.y);
        float2 f0 = __half22float2(p0), f1 = __half22float2(p1);
        acc.x += f0.x; acc.y += f0.y; acc.z += f1.x; acc.w += f1.y;
    }
    if (j < deg) {
        float4 v = gather_row(bk[j], lane);
        acc.x += v.x; acc.y += v.y; acc.z += v.z; acc.w += v.w;
    }
    return acc;
}

__global__ void k_agg(const float* __restrict__ bias) {
    int gw = (blockIdx.x * blockDim.x + threadIdx.x) >> 5;
    int lane = threadIdx.x & 31;
    if (gw >= NN) return;
    int deg = g_cursor[gw];
    float4 acc = agg_node(gw, lane, deg);
    float di = rsqrtf((float)(deg + 1));
    float4 b = ((const float4*)bias)[lane];
    acc.x = fmaxf(di * acc.x + b.x, 0.0f);
    acc.y = fmaxf(di * acc.y + b.y, 0.0f);
    acc.z = fmaxf(di * acc.z + b.z, 0.0f);
    acc.w = fmaxf(di * acc.w + b.w, 0.0f);
    ((float4*)g_buf1)[(size_t)gw * 32 + lane] = acc;
}

__global__ void k_agg_final(const float* __restrict__ bias,
                            const float* __restrict__ Wlin,
                            const float* __restrict__ blin,
                            float* __restrict__ out) {
    int gw = (blockIdx.x * blockDim.x + threadIdx.x) >> 5;
    int lane = threadIdx.x & 31;
    if (gw >= NN) return;
    int deg = g_cursor[gw];
    float4 acc = agg_node(gw, lane, deg);
    float di = rsqrtf((float)(deg + 1));
    float4 b = ((const float4*)bias)[lane];
    acc.x = fmaxf(di * acc.x + b.x, 0.0f);
    acc.y = fmaxf(di * acc.y + b.y, 0.0f);
    acc.z = fmaxf(di * acc.z + b.z, 0.0f);
    acc.w = fmaxf(di * acc.w + b.w, 0.0f);
    float4 wl = ((const float4*)Wlin)[lane];
    float s4 = acc.x * wl.x + acc.y * wl.y + acc.z * wl.z + acc.w * wl.w;
    #pragma unroll
    for (int o = 16; o; o >>= 1) s4 += __shfl_xor_sync(0xFFFFFFFFu, s4, o);
    if (lane == 0) out[gw] = s4 + blin[0];
}

// ---------------- launch (6 kernels, single stream) ----------------
extern "C" void kernel_launch(void* const* d_in, const int* in_sizes, int n_in,
                              void* d_out, int out_size) {
    const float* x  = (const float*)d_in[0];
    const void*  ei = d_in[2];
    int base = (in_sizes[3] == C * C) ? 3 : 4;
    const float* W1   = (const float*)d_in[base + 0];
    const float* b1   = (const float*)d_in[base + 1];
    const float* W2   = (const float*)d_in[base + 2];
    const float* b2   = (const float*)d_in[base + 3];
    const float* Wlin = (const float*)d_in[base + 4];
    const float* blin = (const float*)d_in[base + 5];
    float* out = (float*)d_out;
    (void)n_in; (void)out_size;

    cudaFuncSetAttribute(k_gemm, cudaFuncAttributeMaxDynamicSharedMemorySize, SM_TOTAL);

    k_setup<<<SETUP_B, 256>>>((const unsigned int*)ei, W1, W2);
    k_fill<<<(FILL_T + 255) / 256, 256>>>(ei);

    k_gemm<<<NTILE, 512, SM_TOTAL>>>(x, 0);
    k_agg<<<(NN * 32 + 63) / 64, 64>>>(b1);                 // 2 warps/CTA
    k_gemm<<<NTILE, 512, SM_TOTAL>>>(nullptr, 1);
    k_agg_final<<<(NN * 32 + 63) / 64, 64>>>(b2, Wlin, blin, out);
}

// round 16
// speedup vs baseline: 1.1545x; 1.1545x over previous
#include <cuda_runtime.h>
#include <cuda_fp16.h>
#include <cuda_bf16.h>
#include <cstdint>

#define NN 50000
#define NE 800000
#define C 128
#define M_PAD 50048   /* 391 * 128 */
#define NTILE (M_PAD / 128)   /* 391 */
#define BCAP 64       /* bucket capacity; max in-degree (Poisson mean 16) << 64 */
#define FILL_T (NE / 4)       /* 200000 threads, 4 edges each */
#define FILL_B ((FILL_T + 255) / 256)   /* 782 blocks */

#define PKW 68        /* u32 pitch of one bf16 tile row (136 bf16 = 272 B) */
#define IMG_U32 (128 * PKW)          /* 8704 u32 per 128x128 bf16 image */
#define IMG_BYTES (IMG_U32 * 4)      /* 34816 B */
#define SM_TOTAL (4 * IMG_BYTES)     /* Ahi, Alo, Whi, Wlo = 139264 B */

// ---------------- device scratch (static, no allocation) ----------------
// g_cursor: zero at module load; k_agg_final resets to 0 each launch, so the
// zero invariant holds for the correctness run and every graph replay.
__device__ int      g_cursor[NN];               // post-fill = in-degree
__device__ int      g_bucket[(size_t)NN * BCAP];// per-node src lists (256B/node)
__device__ __half   g_h[(size_t)M_PAD * C];     // dinv-scaled gather table t
__device__ __half   g_bufh[(size_t)M_PAD * C];  // layer-1 activations (fp16)
// W images: [W1hi, W1lo, W2hi, W2lo]; row-major n x k bf16, pitch PKW u32.
__device__ uint32_t g_Wimg[4][IMG_U32];

// ---------------- small helpers ----------------
__device__ __forceinline__ uint32_t smem_u32(const void* p) {
    uint32_t a;
    asm("{ .reg .u64 t; cvta.to.shared.u64 t, %1; cvt.u32.u64 %0, t; }" : "=r"(a) : "l"(p));
    return a;
}
__device__ __forceinline__ uint32_t pack_bf16(float lo_elem, float hi_elem) {
    __nv_bfloat162 t = __floats2bfloat162_rn(lo_elem, hi_elem);  // .x = first arg
    return *reinterpret_cast<uint32_t*>(&t);
}
__device__ __forceinline__ void ldsm_x4(uint32_t* r, uint32_t addr) {
    asm volatile("ldmatrix.sync.aligned.m8n8.x4.shared.b16 {%0,%1,%2,%3}, [%4];"
                 : "=r"(r[0]), "=r"(r[1]), "=r"(r[2]), "=r"(r[3]) : "r"(addr));
}
__device__ __forceinline__ void mma_bf16(float* c, const uint32_t* a, uint32_t b0, uint32_t b1) {
    asm volatile(
        "mma.sync.aligned.m16n8k16.row.col.f32.bf16.bf16.f32 "
        "{%0,%1,%2,%3}, {%4,%5,%6,%7}, {%8,%9}, {%0,%1,%2,%3};"
        : "+f"(c[0]), "+f"(c[1]), "+f"(c[2]), "+f"(c[3])
        : "r"(a[0]), "r"(a[1]), "r"(a[2]), "r"(a[3]), "r"(b0), "r"(b1));
}
__device__ __forceinline__ int edge_at(const void* ei, int is64, long long idx) {
    return is64 ? (int)((const long long*)ei)[idx] : ((const int*)ei)[idx];
}

// ---------------- fill: probe + bucket scatter + W prep (one launch) --------
__global__ void k_fill(const void* __restrict__ ei,
                       const float* __restrict__ W1, const float* __restrict__ W2) {
    __shared__ int s_is64;
    int tx = threadIdx.x;
    int t = blockIdx.x * blockDim.x + tx;

    // per-block dtype probe (8 KB, L2-resident after block 0)
    if (tx < 32) {
        const unsigned int* w = (const unsigned int*)ei;
        unsigned int acc = 0;
        #pragma unroll
        for (int i = 0; i < 32; ++i) acc |= w[2 * (tx + 32 * i) + 1];
        int any = __any_sync(0xFFFFFFFFu, acc != 0);
        if (tx == 0) s_is64 = !any;
    }
    __syncthreads();
    int is64 = s_is64;

    if (t < FILL_T) {
        int s[4], d[4], pos[4];
        #pragma unroll
        for (int k = 0; k < 4; ++k) {
            int e = t + FILL_T * k;                  // coalesced within phase
            s[k] = edge_at(ei, is64, e);
            d[k] = edge_at(ei, is64, (long long)NE + e);
        }
        #pragma unroll
        for (int k = 0; k < 4; ++k)
            pos[k] = atomicAdd(&g_cursor[d[k]], 1);  // 4 independent atomics
        #pragma unroll
        for (int k = 0; k < 4; ++k)
            g_bucket[(size_t)d[k] * BCAP + pos[k]] = s[k];
    }

    // W prep in first 64 blocks: transpose + bf16 hi/lo split
    if (blockIdx.x < 64) {
        int gid = blockIdx.x * 256 + tx;             // 0..16383
        int m  = gid >> 13;
        int p  = gid & 8191;
        int n  = p >> 6;
        int kp = p & 63;
        const float* W = m ? W2 : W1;
        float v0 = W[(2 * kp) * C + n];
        float v1 = W[(2 * kp + 1) * C + n];
        float h0 = __bfloat162float(__float2bfloat16_rn(v0));
        float h1 = __bfloat162float(__float2bfloat16_rn(v1));
        g_Wimg[m * 2 + 0][n * PKW + kp] = pack_bf16(h0, h1);
        g_Wimg[m * 2 + 1][n * PKW + kp] = pack_bf16(v0 - h0, v1 - h1);
    }
}

// ---------------- HMMA GEMM: g_h[tile] = dinv .* (A @ W)  -------------------
// R14 config: 256 threads, 8 warps, warp tile 64x32.
// layer 1: A = fp32 x; layer 2: A = fp16 g_bufh.
__global__ void __launch_bounds__(256, 1) k_gemm(const float* __restrict__ Aext, int wsel) {
    extern __shared__ char smem[];
    uint32_t* Ahi = (uint32_t*)smem;
    uint32_t* Alo = Ahi + IMG_U32;
    const uint32_t sb = smem_u32(smem);
    const int tid = threadIdx.x;
    const int row0 = blockIdx.x * 128;

    #pragma unroll
    for (int i = 0; i < 32; ++i) {
        int p  = tid + 256 * i;        // 0..8191
        int r  = p >> 6;
        int kp = p & 63;
        int grow = row0 + r;
        float2 v = make_float2(0.f, 0.f);
        if (grow < NN) {
            if (Aext) {
                v = ((const float2*)Aext)[(size_t)grow * 64 + kp];
            } else {
                __half2 h2 = ((const __half2*)g_bufh)[(size_t)grow * 64 + kp];
                v = __half22float2(h2);
            }
        }
        float h0 = __bfloat162float(__float2bfloat16_rn(v.x));
        float h1 = __bfloat162float(__float2bfloat16_rn(v.y));
        Ahi[r * PKW + kp] = pack_bf16(h0, h1);
        Alo[r * PKW + kp] = pack_bf16(v.x - h0, v.y - h1);
    }
    {
        const uint4* sh = (const uint4*)g_Wimg[wsel * 2 + 0];
        const uint4* sl = (const uint4*)g_Wimg[wsel * 2 + 1];
        uint4* dh = (uint4*)(smem + 2 * IMG_BYTES);
        uint4* dl = (uint4*)(smem + 3 * IMG_BYTES);
        #pragma unroll
        for (int i = 0; i < 9; ++i) {
            int x = tid + 256 * i;     // 0..2175 uint4
            if (x < IMG_BYTES / 16) { dh[x] = sh[x]; dl[x] = sl[x]; }
        }
    }
    __syncthreads();

    const int wid  = tid >> 5;
    const int lane = tid & 31;
    const int rm = (wid & 1) * 64;     // warp row base
    const int nb = (wid >> 1) * 32;    // warp col base

    const int row_off = (lane & 7) + ((lane >> 3) & 1) * 8;
    const int kqA = lane >> 4;
    uint32_t ao[4];
    #pragma unroll
    for (int mi = 0; mi < 4; ++mi)
        ao[mi] = ((rm + mi * 16 + row_off) * PKW + kqA * 4) * 4;
    const int n_off = (lane & 7) + ((lane & 16) ? 8 : 0);
    const int kqB = (lane >> 3) & 1;
    uint32_t bo[2];
    #pragma unroll
    for (int ni2 = 0; ni2 < 2; ++ni2)
        bo[ni2] = ((nb + ni2 * 16 + n_off) * PKW + kqB * 4) * 4;

    float acc[4][4][4];
    #pragma unroll
    for (int mi = 0; mi < 4; ++mi)
        #pragma unroll
        for (int ni = 0; ni < 4; ++ni)
            #pragma unroll
            for (int q = 0; q < 4; ++q) acc[mi][ni][q] = 0.0f;

    const uint32_t pa[3] = {0, 0, 1}, pb[3] = {0, 1, 0};
    #pragma unroll
    for (int pr = 0; pr < 3; ++pr) {
        uint32_t abase = sb + pa[pr] * IMG_BYTES;
        uint32_t bbase = sb + 2 * IMG_BYTES + pb[pr] * IMG_BYTES;
        #pragma unroll
        for (int ks = 0; ks < 8; ++ks) {
            uint32_t koff = ks * 32;   // 16 bf16 = 32 B
            uint32_t a[4][4], b[2][4];
            #pragma unroll
            for (int mi = 0; mi < 4; ++mi) ldsm_x4(a[mi], abase + ao[mi] + koff);
            #pragma unroll
            for (int ni2 = 0; ni2 < 2; ++ni2) ldsm_x4(b[ni2], bbase + bo[ni2] + koff);
            #pragma unroll
            for (int mi = 0; mi < 4; ++mi)
                #pragma unroll
                for (int ni = 0; ni < 4; ++ni)
                    mma_bf16(acc[mi][ni], a[mi],
                             b[ni >> 1][2 * (ni & 1)], b[ni >> 1][2 * (ni & 1) + 1]);
        }
    }

    // epilogue: dinv[row] = rsqrt(deg+1) straight from cursor; store fp16 table
    #pragma unroll
    for (int mi = 0; mi < 4; ++mi) {
        int row = row0 + rm + mi * 16 + (lane >> 2);
        float dv0 = (row     < NN) ? rsqrtf((float)(g_cursor[row]     + 1)) : 0.0f;
        float dv1 = (row + 8 < NN) ? rsqrtf((float)(g_cursor[row + 8] + 1)) : 0.0f;
        #pragma unroll
        for (int ni = 0; ni < 4; ++ni) {
            int col = nb + ni * 8 + (lane & 3) * 2;
            __half2 lo = __float22half2_rn(make_float2(acc[mi][ni][0] * dv0,
                                                       acc[mi][ni][1] * dv0));
            __half2 hi = __float22half2_rn(make_float2(acc[mi][ni][2] * dv1,
                                                       acc[mi][ni][3] * dv1));
            *(__half2*)(g_h + (size_t)row * C + col)       = lo;
            *(__half2*)(g_h + (size_t)(row + 8) * C + col) = hi;
        }
    }
}

// ---------------- Aggregation: warp per node, fp16-pair pre-sum -------------
// out[d] = relu( dinv[d] * (Σ_in t[src] + t[d]) + b )
__device__ __forceinline__ float4 gather_row(int row, int lane) {
    uint2 u = *(const uint2*)(g_h + (size_t)row * C + lane * 4);
    __half2 a = *(__half2*)&u.x, b = *(__half2*)&u.y;
    float2 f0 = __half22float2(a), f1 = __half22float2(b);
    return make_float4(f0.x, f0.y, f1.x, f1.y);
}
__device__ __forceinline__ float4 agg_node(int gw, int lane, int deg) {
    float4 acc = gather_row(gw, lane);              // self-loop term t[d]
    const int* __restrict__ bk = g_bucket + (size_t)gw * BCAP;
    const char* tb = (const char*)g_h + lane * 8;
    int j = 0;
    #pragma unroll 2
    for (; j + 2 <= deg; j += 2) {
        uint2 ua = *(const uint2*)(tb + (size_t)bk[j]     * 256);
        uint2 ub = *(const uint2*)(tb + (size_t)bk[j + 1] * 256);
        __half2 p0 = __hadd2(*(__half2*)&ua.x, *(__half2*)&ub.x);
        __half2 p1 = __hadd2(*(__half2*)&ua.y, *(__half2*)&ub.y);
        float2 f0 = __half22float2(p0), f1 = __half22float2(p1);
        acc.x += f0.x; acc.y += f0.y; acc.z += f1.x; acc.w += f1.y;
    }
    if (j < deg) {
        float4 v = gather_row(bk[j], lane);
        acc.x += v.x; acc.y += v.y; acc.z += v.z; acc.w += v.w;
    }
    return acc;
}

__global__ void k_agg(const float* __restrict__ bias) {
    int gw = (blockIdx.x * blockDim.x + threadIdx.x) >> 5;
    int lane = threadIdx.x & 31;
    if (gw >= NN) return;
    int deg = g_cursor[gw];
    float4 acc = agg_node(gw, lane, deg);
    float di = rsqrtf((float)(deg + 1));
    float4 b = ((const float4*)bias)[lane];
    acc.x = fmaxf(di * acc.x + b.x, 0.0f);
    acc.y = fmaxf(di * acc.y + b.y, 0.0f);
    acc.z = fmaxf(di * acc.z + b.z, 0.0f);
    acc.w = fmaxf(di * acc.w + b.w, 0.0f);
    __half2 lo = __float22half2_rn(make_float2(acc.x, acc.y));
    __half2 hi = __float22half2_rn(make_float2(acc.z, acc.w));
    uint2 pk = { *(uint32_t*)&lo, *(uint32_t*)&hi };
    *(uint2*)(g_bufh + (size_t)gw * C + lane * 4) = pk;
}

__global__ void k_agg_final(const float* __restrict__ bias,
                            const float* __restrict__ Wlin,
                            const float* __restrict__ blin,
                            float* __restrict__ out) {
    int gw = (blockIdx.x * blockDim.x + threadIdx.x) >> 5;
    int lane = threadIdx.x & 31;
    if (gw >= NN) return;
    int deg = g_cursor[gw];
    float4 acc = agg_node(gw, lane, deg);
    if (lane == 0) g_cursor[gw] = 0;   // restore zero invariant for next launch
    float di = rsqrtf((float)(deg + 1));
    float4 b = ((const float4*)bias)[lane];
    acc.x = fmaxf(di * acc.x + b.x, 0.0f);
    acc.y = fmaxf(di * acc.y + b.y, 0.0f);
    acc.z = fmaxf(di * acc.z + b.z, 0.0f);
    acc.w = fmaxf(di * acc.w + b.w, 0.0f);
    float4 wl = ((const float4*)Wlin)[lane];
    float s4 = acc.x * wl.x + acc.y * wl.y + acc.z * wl.z + acc.w * wl.w;
    #pragma unroll
    for (int o = 16; o; o >>= 1) s4 += __shfl_xor_sync(0xFFFFFFFFu, s4, o);
    if (lane == 0) out[gw] = s4 + blin[0];
}

// ---------------- launch (5 kernels, single stream) ----------------
extern "C" void kernel_launch(void* const* d_in, const int* in_sizes, int n_in,
                              void* d_out, int out_size) {
    const float* x  = (const float*)d_in[0];
    const void*  ei = d_in[2];
    int base = (in_sizes[3] == C * C) ? 3 : 4;
    const float* W1   = (const float*)d_in[base + 0];
    const float* b1   = (const float*)d_in[base + 1];
    const float* W2   = (const float*)d_in[base + 2];
    const float* b2   = (const float*)d_in[base + 3];
    const float* Wlin = (const float*)d_in[base + 4];
    const float* blin = (const float*)d_in[base + 5];
    float* out = (float*)d_out;
    (void)n_in; (void)out_size;

    cudaFuncSetAttribute(k_gemm, cudaFuncAttributeMaxDynamicSharedMemorySize, SM_TOTAL);

    k_fill<<<FILL_B, 256>>>(ei, W1, W2);

    k_gemm<<<NTILE, 256, SM_TOTAL>>>(x, 0);
    k_agg<<<(NN * 32 + 63) / 64, 64>>>(b1);                 // 2 warps/CTA
    k_gemm<<<NTILE, 256, SM_TOTAL>>>(nullptr, 1);
    k_agg_final<<<(NN * 32 + 63) / 64, 64>>>(b2, Wlin, blin, out);
}